// round 1
// baseline (speedup 1.0000x reference)
#include <cuda_runtime.h>
#include <math.h>

// Problem constants
#define NROWS 2048
#define NN    2048
#define DIN   256
#define H     32
#define DOUT  256

// Scratch (device globals: no allocation allowed)
__device__ float g_xatt[NROWS * H];
__device__ float g_natt[NN * H];
__device__ float g_agg[NROWS * DIN];

// ---------------------------------------------------------------------------
// Kernel 1: 2-layer MLP  att = tanh(in @ w1 + b1) @ w2 + b2
// 256 threads = 8 rows x 32 hidden units. which: 0 -> g_xatt, 1 -> g_natt
// ---------------------------------------------------------------------------
__global__ void att_mlp_kernel(const float* __restrict__ in,
                               const float* __restrict__ w1,
                               const float* __restrict__ b1,
                               const float* __restrict__ w2,
                               const float* __restrict__ b2,
                               int which) {
    __shared__ float w1s[DIN * H];   // 32 KB
    __shared__ float w2s[H * H];     // 4 KB
    __shared__ float b1s[H], b2s[H];
    __shared__ float xs[8 * DIN];    // 8 KB
    __shared__ float t1s[8 * 33];

    const int tid = threadIdx.x;
    const int row0 = blockIdx.x * 8;

    for (int i = tid; i < DIN * H; i += 256) w1s[i] = w1[i];
    for (int i = tid; i < H * H; i += 256)   w2s[i] = w2[i];
    if (tid < H) { b1s[tid] = b1[tid]; b2s[tid] = b2[tid]; }
    for (int i = tid; i < 8 * DIN; i += 256) xs[i] = in[row0 * DIN + i];
    __syncthreads();

    const int r = tid >> 5;   // row within block (whole warp shares one row)
    const int h = tid & 31;   // hidden unit

    float acc = b1s[h];
    #pragma unroll 8
    for (int k = 0; k < DIN; k++)
        acc += xs[r * DIN + k] * w1s[k * H + h];

    t1s[r * 33 + h] = tanhf(acc);
    __syncwarp();

    float acc2 = b2s[h];
    #pragma unroll
    for (int kk = 0; kk < H; kk++)
        acc2 += t1s[r * 33 + kk] * w2s[kk * H + h];

    float* out = which ? g_natt : g_xatt;
    out[(row0 + r) * H + h] = acc2;
}

// ---------------------------------------------------------------------------
// Kernel 2: fused  s = (x_att @ neib_att^T) * mask ; softmax(row) ;
//           agg = sigmoid(softmax @ neibs)          (flash-attention style)
// Block: 256 threads, BM=16 target rows, BN=32 neighbor tile.
// acc mapping: 8 row-groups (2 rows each) x 32 col-groups (8 cols each).
// ---------------------------------------------------------------------------
#define BM 16
#define BN 32

__global__ void flash_agg_kernel(const float* __restrict__ neibs,
                                 const float* __restrict__ mask) {
    __shared__ float xa[BM * H];        // 2 KB
    __shared__ float na[BN * 33];       // padded, ~4.2 KB
    __shared__ float ps[BM * 33];       // ~2.1 KB
    __shared__ float nb[BN * DIN];      // 32 KB
    __shared__ float m_s[BM], l_s[BM], alpha_s[BM];

    const int tid  = threadIdx.x;
    const int row0 = blockIdx.x * BM;

    // accumulator mapping
    const int rg  = tid >> 5;           // 0..7
    const int cg  = tid & 31;           // 0..31
    const int r0a = rg * 2, r1a = rg * 2 + 1;
    const int c0  = cg * 8;

    // s-compute mapping
    const int sr = tid >> 4;            // 0..15 (row)
    const int jg = tid & 15;            // 0..15 (j-group, 2 j's each)
    const int j0 = jg * 2;

    for (int i = tid; i < BM * H; i += 256) xa[i] = g_xatt[row0 * H + i];
    if (tid < BM) { m_s[tid] = -INFINITY; l_s[tid] = 0.0f; }

    float acc0[8], acc1[8];
    #pragma unroll
    for (int i = 0; i < 8; i++) { acc0[i] = 0.0f; acc1[i] = 0.0f; }

    __syncthreads();

    for (int t = 0; t < NN / BN; t++) {
        const int jbase = t * BN;

        // stage neib_att tile (padded) and neibs tile (float4)
        for (int i = tid; i < BN * H; i += 256) {
            int jr = i >> 5, hh = i & 31;
            na[jr * 33 + hh] = g_natt[(jbase + jr) * H + hh];
        }
        {
            const float4* src = (const float4*)(neibs + (size_t)jbase * DIN);
            float4* dst = (float4*)nb;
            #pragma unroll
            for (int i = tid; i < BN * DIN / 4; i += 256) dst[i] = src[i];
        }
        __syncthreads();

        // scores for 2 j's per thread
        float sv0 = 0.0f, sv1 = 0.0f;
        #pragma unroll 8
        for (int hh = 0; hh < H; hh++) {
            float xv = xa[sr * H + hh];
            sv0 += xv * na[j0 * 33 + hh];
            sv1 += xv * na[(j0 + 1) * 33 + hh];
        }
        const float* mrow = mask + (size_t)(row0 + sr) * NN + jbase;
        sv0 *= mrow[j0];
        sv1 *= mrow[j0 + 1];

        // tile max over the 16-lane row group
        float tm = fmaxf(sv0, sv1);
        #pragma unroll
        for (int d = 8; d >= 1; d >>= 1)
            tm = fmaxf(tm, __shfl_xor_sync(0xffffffffu, tm, d));

        float m_old = m_s[sr];
        float m_new = fmaxf(m_old, tm);
        float p0 = __expf(sv0 - m_new);
        float p1 = __expf(sv1 - m_new);
        ps[sr * 33 + j0]     = p0;
        ps[sr * 33 + j0 + 1] = p1;

        float psum = p0 + p1;
        #pragma unroll
        for (int d = 8; d >= 1; d >>= 1)
            psum += __shfl_xor_sync(0xffffffffu, psum, d);

        __syncwarp();
        if (jg == 0) {
            float alpha = __expf(m_old - m_new);   // 0 on first tile (m_old=-inf)
            l_s[sr] = l_s[sr] * alpha + psum;
            alpha_s[sr] = alpha;
            m_s[sr] = m_new;
        }
        __syncthreads();

        // rescale + accumulate p @ neibs_tile
        const float a0 = alpha_s[r0a];
        const float a1 = alpha_s[r1a];
        #pragma unroll
        for (int i = 0; i < 8; i++) { acc0[i] *= a0; acc1[i] *= a1; }

        #pragma unroll 4
        for (int j = 0; j < BN; j++) {
            float p0v = ps[r0a * 33 + j];
            float p1v = ps[r1a * 33 + j];
            float4 nA = *(const float4*)(nb + j * DIN + c0);
            float4 nB = *(const float4*)(nb + j * DIN + c0 + 4);
            acc0[0] += p0v * nA.x; acc0[1] += p0v * nA.y;
            acc0[2] += p0v * nA.z; acc0[3] += p0v * nA.w;
            acc0[4] += p0v * nB.x; acc0[5] += p0v * nB.y;
            acc0[6] += p0v * nB.z; acc0[7] += p0v * nB.w;
            acc1[0] += p1v * nA.x; acc1[1] += p1v * nA.y;
            acc1[2] += p1v * nA.z; acc1[3] += p1v * nA.w;
            acc1[4] += p1v * nB.x; acc1[5] += p1v * nB.y;
            acc1[6] += p1v * nB.z; acc1[7] += p1v * nB.w;
        }
        __syncthreads();
    }

    // epilogue: agg = sigmoid(acc / l)
    const float inv0 = 1.0f / l_s[r0a];
    const float inv1 = 1.0f / l_s[r1a];
    float* o0 = g_agg + (size_t)(row0 + r0a) * DIN + c0;
    float* o1 = g_agg + (size_t)(row0 + r1a) * DIN + c0;
    #pragma unroll
    for (int i = 0; i < 8; i++) {
        o0[i] = 1.0f / (1.0f + __expf(-acc0[i] * inv0));
        o1[i] = 1.0f / (1.0f + __expf(-acc1[i] * inv1));
    }
}

// ---------------------------------------------------------------------------
// Kernel 3: out = sigmoid([x | agg] @ fcx_w + fcx_b)   (K = 512 tiled GEMM)
// ---------------------------------------------------------------------------
__global__ void fc_out_kernel(const float* __restrict__ x,
                              const float* __restrict__ fcw,
                              const float* __restrict__ fcb,
                              float* __restrict__ out) {
    __shared__ float At[BM * 33];      // ~2.1 KB
    __shared__ float Wt[32 * DOUT];    // 32 KB

    const int tid  = threadIdx.x;
    const int row0 = blockIdx.x * BM;
    const int rg  = tid >> 5;
    const int cg  = tid & 31;
    const int r0a = rg * 2, r1a = rg * 2 + 1;
    const int c0  = cg * 8;

    float acc0[8], acc1[8];
    #pragma unroll
    for (int i = 0; i < 8; i++) { acc0[i] = 0.0f; acc1[i] = 0.0f; }

    for (int kt = 0; kt < 16; kt++) {
        const int kbase = kt * 32;
        // stage A tile (from x for k<256, from g_agg for k>=256)
        for (int i = tid; i < BM * 32; i += 256) {
            int rr = i >> 5, kk = i & 31;
            float v;
            if (kt < 8)
                v = x[(size_t)(row0 + rr) * DIN + kbase + kk];
            else
                v = g_agg[(size_t)(row0 + rr) * DIN + (kbase - 256) + kk];
            At[rr * 33 + kk] = v;
        }
        // stage W tile
        {
            const float4* src = (const float4*)(fcw + (size_t)kbase * DOUT);
            float4* dst = (float4*)Wt;
            #pragma unroll
            for (int i = tid; i < 32 * DOUT / 4; i += 256) dst[i] = src[i];
        }
        __syncthreads();

        #pragma unroll 8
        for (int k = 0; k < 32; k++) {
            float a0 = At[r0a * 33 + k];
            float a1 = At[r1a * 33 + k];
            float4 wA = *(const float4*)(Wt + k * DOUT + c0);
            float4 wB = *(const float4*)(Wt + k * DOUT + c0 + 4);
            acc0[0] += a0 * wA.x; acc0[1] += a0 * wA.y;
            acc0[2] += a0 * wA.z; acc0[3] += a0 * wA.w;
            acc0[4] += a0 * wB.x; acc0[5] += a0 * wB.y;
            acc0[6] += a0 * wB.z; acc0[7] += a0 * wB.w;
            acc1[0] += a1 * wA.x; acc1[1] += a1 * wA.y;
            acc1[2] += a1 * wA.z; acc1[3] += a1 * wA.w;
            acc1[4] += a1 * wB.x; acc1[5] += a1 * wB.y;
            acc1[6] += a1 * wB.z; acc1[7] += a1 * wB.w;
        }
        __syncthreads();
    }

    float* p0 = out + (size_t)(row0 + r0a) * DOUT + c0;
    float* p1 = out + (size_t)(row0 + r1a) * DOUT + c0;
    #pragma unroll
    for (int i = 0; i < 8; i++) {
        float b = fcb[c0 + i];
        p0[i] = 1.0f / (1.0f + __expf(-(acc0[i] + b)));
        p1[i] = 1.0f / (1.0f + __expf(-(acc1[i] + b)));
    }
}

// ---------------------------------------------------------------------------
extern "C" void kernel_launch(void* const* d_in, const int* in_sizes, int n_in,
                              void* d_out, int out_size) {
    (void)in_sizes; (void)n_in; (void)out_size;
    const float* x      = (const float*)d_in[0];
    const float* neibs  = (const float*)d_in[1];
    // d_in[2] = edge_emb: dead code in the reference, intentionally untouched
    const float* mask   = (const float*)d_in[3];
    const float* ax_w1  = (const float*)d_in[4];
    const float* ax_b1  = (const float*)d_in[5];
    const float* ax_w2  = (const float*)d_in[6];
    const float* ax_b2  = (const float*)d_in[7];
    const float* an_w1  = (const float*)d_in[8];
    const float* an_b1  = (const float*)d_in[9];
    const float* an_w2  = (const float*)d_in[10];
    const float* an_b2  = (const float*)d_in[11];
    // d_in[12..15] = ae_* : dead code
    const float* fcx_w  = (const float*)d_in[16];
    const float* fcx_b  = (const float*)d_in[17];
    float* out = (float*)d_out;

    att_mlp_kernel<<<NROWS / 8, 256>>>(x, ax_w1, ax_b1, ax_w2, ax_b2, 0);
    att_mlp_kernel<<<NN / 8, 256>>>(neibs, an_w1, an_b1, an_w2, an_b2, 1);
    flash_agg_kernel<<<NROWS / BM, 256>>>(neibs, mask);
    fc_out_kernel<<<NROWS / BM, 256>>>(x, fcx_w, fcx_b, out);
}

// round 3
// speedup vs baseline: 2.3528x; 2.3528x over previous
#include <cuda_runtime.h>
#include <math.h>

// Problem constants
#define NROWS 2048
#define NN    2048
#define DIN   256
#define H     32
#define DOUT  256

#define NSPLIT 8
#define CHUNK  (NN / NSPLIT)     // 256 neighbors per split
#define BM 32                    // rows per flash block
#define BN 32                    // neighbor tile

// Scratch (device globals: no allocation allowed)
__device__ float g_xatt[NROWS * H];
__device__ float g_natt[NN * H];
__device__ float g_agg[NROWS * DIN];
__device__ float g_pacc[NSPLIT * NROWS * DIN];   // 16 MB partial accumulators
__device__ float g_pm[NSPLIT * NROWS];
__device__ float g_pl[NSPLIT * NROWS];

// ---------------------------------------------------------------------------
// Kernel 1: both attention MLPs in one launch (grid = 512).
// att = tanh(in @ w1 + b1) @ w2 + b2 ; blocks [0,256) -> x, [256,512) -> neibs
// ---------------------------------------------------------------------------
__global__ __launch_bounds__(256) void att_mlp_kernel(
        const float* __restrict__ x, const float* __restrict__ neibs,
        const float* __restrict__ xw1, const float* __restrict__ xb1,
        const float* __restrict__ xw2, const float* __restrict__ xb2,
        const float* __restrict__ nw1, const float* __restrict__ nb1,
        const float* __restrict__ nw2, const float* __restrict__ nb2) {
    __shared__ float w1s[DIN * H];   // 32 KB
    __shared__ float w2s[H * H];     // 4 KB
    __shared__ float b1s[H], b2s[H];
    __shared__ float xs[8 * DIN];    // 8 KB
    __shared__ float t1s[8 * 33];

    const int tid = threadIdx.x;
    const int which = blockIdx.x >= 256;
    const int row0 = (blockIdx.x & 255) * 8;

    const float* in = which ? neibs : x;
    const float* w1 = which ? nw1 : xw1;
    const float* b1 = which ? nb1 : xb1;
    const float* w2 = which ? nw2 : xw2;
    const float* b2 = which ? nb2 : xb2;

    for (int i = tid; i < DIN * H; i += 256) w1s[i] = w1[i];
    for (int i = tid; i < H * H; i += 256)   w2s[i] = w2[i];
    if (tid < H) { b1s[tid] = b1[tid]; b2s[tid] = b2[tid]; }
    for (int i = tid; i < 8 * DIN; i += 256) xs[i] = in[row0 * DIN + i];
    __syncthreads();

    const int r = tid >> 5;   // row within block (warp shares one row)
    const int h = tid & 31;   // hidden unit

    float acc = b1s[h];
    #pragma unroll 8
    for (int k = 0; k < DIN; k++)
        acc += xs[r * DIN + k] * w1s[k * H + h];

    t1s[r * 33 + h] = tanhf(acc);
    __syncwarp();

    float acc2 = b2s[h];
    #pragma unroll
    for (int kk = 0; kk < H; kk++)
        acc2 += t1s[r * 33 + kk] * w2s[kk * H + h];

    float* out = which ? g_natt : g_xatt;
    out[(row0 + r) * H + h] = acc2;
}

// ---------------------------------------------------------------------------
// Kernel 2: split-K flash aggregation. Each block: 32 target rows x 256
// neighbors (one split), online softmax, partial (m, l, acc) to globals.
// Grid = 64 row-blocks * 8 splits = 512 blocks, 256 threads.
// ---------------------------------------------------------------------------
__global__ __launch_bounds__(256) void flash_part_kernel(
        const float* __restrict__ neibs, const float* __restrict__ mask) {
    __shared__ float naT[H * 36];       // transposed neib_att tile, padded
    __shared__ float ps[BM * 33];       // softmax weights
    __shared__ float nb[BN * DIN];      // 32 KB neighbor features
    __shared__ float m_s[BM], l_s[BM], alpha_s[BM];

    const int tid   = threadIdx.x;
    const int split = blockIdx.x & (NSPLIT - 1);
    const int row0  = (blockIdx.x >> 3) * BM;
    const int jstart = split * CHUNK;

    // score-phase mapping: 32 rows x 8 j-groups (4 j each)
    const int srow = tid >> 3;
    const int jg   = tid & 7;
    const int j0   = jg * 4;

    // acc-phase mapping: warp rg owns rows rg*4..rg*4+3; lane cg owns cols
    // cg*4 and 128+cg*4 (conflict-free float4)
    const int rg = tid >> 5;
    const int cg = tid & 31;

    // cache this thread's x_att row in registers (fixed across tiles)
    float xr[H];
    {
        const float4* src = (const float4*)(g_xatt + (size_t)(row0 + srow) * H);
        #pragma unroll
        for (int i = 0; i < H / 4; i++) {
            float4 v = src[i];
            xr[i * 4 + 0] = v.x; xr[i * 4 + 1] = v.y;
            xr[i * 4 + 2] = v.z; xr[i * 4 + 3] = v.w;
        }
    }
    if (tid < BM) { m_s[tid] = -INFINITY; l_s[tid] = 0.0f; }

    float acc[4][8];
    #pragma unroll
    for (int i = 0; i < 4; i++)
        #pragma unroll
        for (int c = 0; c < 8; c++) acc[i][c] = 0.0f;

    __syncthreads();

    for (int t = 0; t < CHUNK / BN; t++) {
        const int jcol0 = jstart + t * BN;

        // stage neib_att tile transposed: naT[h][j]
        for (int i = tid; i < BN * H; i += 256) {
            int j = i & 31, hh = i >> 5;
            naT[hh * 36 + j] = g_natt[(size_t)(jcol0 + j) * H + hh];
        }
        // stage neighbor features (float4)
        {
            const float4* src = (const float4*)(neibs + (size_t)jcol0 * DIN);
            float4* dst = (float4*)nb;
            #pragma unroll
            for (int i = tid; i < BN * DIN / 4; i += 256) dst[i] = src[i];
        }
        __syncthreads();

        // ---- scores: 4 j's per thread ----
        float s0 = 0.f, s1 = 0.f, s2 = 0.f, s3 = 0.f;
        #pragma unroll
        for (int hh = 0; hh < H; hh++) {
            float4 nv = *(const float4*)(naT + hh * 36 + j0);
            float xv = xr[hh];
            s0 += xv * nv.x; s1 += xv * nv.y;
            s2 += xv * nv.z; s3 += xv * nv.w;
        }
        {
            float4 mv = *(const float4*)(mask + (size_t)(row0 + srow) * NN + jcol0 + j0);
            s0 *= mv.x; s1 *= mv.y; s2 *= mv.z; s3 *= mv.w;
        }

        // row max over the 8-lane group
        float tm = fmaxf(fmaxf(s0, s1), fmaxf(s2, s3));
        #pragma unroll
        for (int d = 4; d >= 1; d >>= 1)
            tm = fmaxf(tm, __shfl_xor_sync(0xffffffffu, tm, d));

        float m_old = m_s[srow];
        float m_new = fmaxf(m_old, tm);
        float p0 = __expf(s0 - m_new);
        float p1 = __expf(s1 - m_new);
        float p2 = __expf(s2 - m_new);
        float p3 = __expf(s3 - m_new);
        ps[srow * 33 + j0 + 0] = p0;
        ps[srow * 33 + j0 + 1] = p1;
        ps[srow * 33 + j0 + 2] = p2;
        ps[srow * 33 + j0 + 3] = p3;

        float psum = (p0 + p1) + (p2 + p3);
        #pragma unroll
        for (int d = 4; d >= 1; d >>= 1)
            psum += __shfl_xor_sync(0xffffffffu, psum, d);

        if (jg == 0) {
            float alpha = __expf(m_old - m_new);   // 0 on first tile
            l_s[srow] = l_s[srow] * alpha + psum;
            alpha_s[srow] = alpha;
            m_s[srow] = m_new;
        }
        __syncwarp();   // softmax state is warp-private (warp owns its 4 rows)

        // ---- rescale + accumulate p @ neibs_tile ----
        #pragma unroll
        for (int i = 0; i < 4; i++) {
            float a = alpha_s[rg * 4 + i];
            #pragma unroll
            for (int c = 0; c < 8; c++) acc[i][c] *= a;
        }

        #pragma unroll 4
        for (int j = 0; j < BN; j++) {
            float4 nA = *(const float4*)(nb + j * DIN + cg * 4);
            float4 nB = *(const float4*)(nb + j * DIN + 128 + cg * 4);
            #pragma unroll
            for (int i = 0; i < 4; i++) {
                float p = ps[(rg * 4 + i) * 33 + j];   // broadcast
                acc[i][0] += p * nA.x; acc[i][1] += p * nA.y;
                acc[i][2] += p * nA.z; acc[i][3] += p * nA.w;
                acc[i][4] += p * nB.x; acc[i][5] += p * nB.y;
                acc[i][6] += p * nB.z; acc[i][7] += p * nB.w;
            }
        }
        __syncthreads();   // before overwriting naT/nb next tile
    }

    // partial outputs (unnormalized, scaled to local max)
    #pragma unroll
    for (int i = 0; i < 4; i++) {
        const size_t base = ((size_t)split * NROWS + row0 + rg * 4 + i) * DIN;
        float4 vA = make_float4(acc[i][0], acc[i][1], acc[i][2], acc[i][3]);
        float4 vB = make_float4(acc[i][4], acc[i][5], acc[i][6], acc[i][7]);
        *(float4*)(g_pacc + base + cg * 4) = vA;
        *(float4*)(g_pacc + base + 128 + cg * 4) = vB;
    }
    if (jg == 0) {
        g_pm[split * NROWS + row0 + srow] = m_s[srow];
        g_pl[split * NROWS + row0 + srow] = l_s[srow];
    }
}

// ---------------------------------------------------------------------------
// Kernel 3: combine split partials -> agg = sigmoid(softmax @ neibs)
// Grid = 256 blocks x 256 threads, 8 rows per block.
// ---------------------------------------------------------------------------
__global__ __launch_bounds__(256) void combine_kernel() {
    const int tid  = threadIdx.x;
    const int row  = blockIdx.x * 8 + (tid >> 5);
    const int lane = tid & 31;

    float M = -INFINITY;
    #pragma unroll
    for (int s = 0; s < NSPLIT; s++)
        M = fmaxf(M, g_pm[s * NROWS + row]);

    float w[NSPLIT];
    float L = 0.0f;
    #pragma unroll
    for (int s = 0; s < NSPLIT; s++) {
        w[s] = __expf(g_pm[s * NROWS + row] - M);
        L += g_pl[s * NROWS + row] * w[s];
    }
    const float invL = 1.0f / L;

    #pragma unroll
    for (int half = 0; half < 2; half++) {
        const int c = half * 128 + lane * 4;
        float4 a = make_float4(0.f, 0.f, 0.f, 0.f);
        #pragma unroll
        for (int s = 0; s < NSPLIT; s++) {
            float4 v = *(const float4*)(g_pacc + ((size_t)s * NROWS + row) * DIN + c);
            a.x += w[s] * v.x; a.y += w[s] * v.y;
            a.z += w[s] * v.z; a.w += w[s] * v.w;
        }
        float4 o;
        o.x = 1.0f / (1.0f + __expf(-a.x * invL));
        o.y = 1.0f / (1.0f + __expf(-a.y * invL));
        o.z = 1.0f / (1.0f + __expf(-a.z * invL));
        o.w = 1.0f / (1.0f + __expf(-a.w * invL));
        *(float4*)(g_agg + (size_t)row * DIN + c) = o;
    }
}

// ---------------------------------------------------------------------------
// Kernel 4: out = sigmoid([x | agg] @ fcx_w + fcx_b)
// 32x64 output tiles, grid = 64*4 = 256 blocks, 256 threads, 8 acc/thread.
// ---------------------------------------------------------------------------
__global__ __launch_bounds__(256) void fc_out_kernel(
        const float* __restrict__ x, const float* __restrict__ fcw,
        const float* __restrict__ fcb, float* __restrict__ out) {
    __shared__ float At[32 * 33];     // ~4.2 KB
    __shared__ float Wt[32 * 64];     // 8 KB

    const int tid  = threadIdx.x;
    const int row0 = (blockIdx.x >> 2) * 32;
    const int col0 = (blockIdx.x & 3) * 64;

    const int rp = tid >> 4;          // 0..15 -> rows 2rp, 2rp+1
    const int cq = tid & 15;          // 0..15 -> cols cq*4

    float acc0[4] = {0.f, 0.f, 0.f, 0.f};
    float acc1[4] = {0.f, 0.f, 0.f, 0.f};

    for (int kt = 0; kt < 16; kt++) {
        const int kbase = kt * 32;
        // stage A tile (x for k<256, g_agg for k>=256)
        for (int i = tid; i < 32 * 32; i += 256) {
            int rr = i >> 5, kk = i & 31;
            float v;
            if (kt < 8)
                v = x[(size_t)(row0 + rr) * DIN + kbase + kk];
            else
                v = g_agg[(size_t)(row0 + rr) * DIN + (kbase - 256) + kk];
            At[rr * 33 + kk] = v;
        }
        // stage W tile (32 k x 64 cols)
        #pragma unroll
        for (int i = tid; i < 32 * 64 / 4; i += 256) {
            int kk = i >> 4, cc = (i & 15) * 4;
            *(float4*)(Wt + kk * 64 + cc) =
                *(const float4*)(fcw + (size_t)(kbase + kk) * DOUT + col0 + cc);
        }
        __syncthreads();

        #pragma unroll 8
        for (int k = 0; k < 32; k++) {
            float a0 = At[(2 * rp) * 33 + k];
            float a1 = At[(2 * rp + 1) * 33 + k];
            float4 wv = *(const float4*)(Wt + k * 64 + cq * 4);
            acc0[0] += a0 * wv.x; acc0[1] += a0 * wv.y;
            acc0[2] += a0 * wv.z; acc0[3] += a0 * wv.w;
            acc1[0] += a1 * wv.x; acc1[1] += a1 * wv.y;
            acc1[2] += a1 * wv.z; acc1[3] += a1 * wv.w;
        }
        __syncthreads();
    }

    float4 b = *(const float4*)(fcb + col0 + cq * 4);
    float4 o0, o1;
    o0.x = 1.0f / (1.0f + __expf(-(acc0[0] + b.x)));
    o0.y = 1.0f / (1.0f + __expf(-(acc0[1] + b.y)));
    o0.z = 1.0f / (1.0f + __expf(-(acc0[2] + b.z)));
    o0.w = 1.0f / (1.0f + __expf(-(acc0[3] + b.w)));
    o1.x = 1.0f / (1.0f + __expf(-(acc1[0] + b.x)));
    o1.y = 1.0f / (1.0f + __expf(-(acc1[1] + b.y)));
    o1.z = 1.0f / (1.0f + __expf(-(acc1[2] + b.z)));
    o1.w = 1.0f / (1.0f + __expf(-(acc1[3] + b.w)));
    *(float4*)(out + (size_t)(row0 + 2 * rp) * DOUT + col0 + cq * 4) = o0;
    *(float4*)(out + (size_t)(row0 + 2 * rp + 1) * DOUT + col0 + cq * 4) = o1;
}

// ---------------------------------------------------------------------------
extern "C" void kernel_launch(void* const* d_in, const int* in_sizes, int n_in,
                              void* d_out, int out_size) {
    (void)in_sizes; (void)n_in; (void)out_size;
    const float* x      = (const float*)d_in[0];
    const float* neibs  = (const float*)d_in[1];
    // d_in[2] = edge_emb: dead code in the reference, intentionally untouched
    const float* mask   = (const float*)d_in[3];
    const float* ax_w1  = (const float*)d_in[4];
    const float* ax_b1  = (const float*)d_in[5];
    const float* ax_w2  = (const float*)d_in[6];
    const float* ax_b2  = (const float*)d_in[7];
    const float* an_w1  = (const float*)d_in[8];
    const float* an_b1  = (const float*)d_in[9];
    const float* an_w2  = (const float*)d_in[10];
    const float* an_b2  = (const float*)d_in[11];
    // d_in[12..15] = ae_* : dead code
    const float* fcx_w  = (const float*)d_in[16];
    const float* fcx_b  = (const float*)d_in[17];
    float* out = (float*)d_out;

    att_mlp_kernel<<<512, 256>>>(x, neibs, ax_w1, ax_b1, ax_w2, ax_b2,
                                 an_w1, an_b1, an_w2, an_b2);
    flash_part_kernel<<<(NROWS / BM) * NSPLIT, 256>>>(neibs, mask);
    combine_kernel<<<NROWS / 8, 256>>>();
    fc_out_kernel<<<(NROWS / 32) * (DOUT / 64), 256>>>(x, fcx_w, fcx_b, out);
}

// round 6
// speedup vs baseline: 2.6232x; 1.1149x over previous
#include <cuda_runtime.h>
#include <math.h>

// Problem constants
#define NROWS 2048
#define NN    2048
#define DIN   256
#define H     32
#define DOUT  256

#define NSPLIT 8
#define CHUNK  (NN / NSPLIT)     // 256 neighbors per split
#define BM 32                    // rows per flash block
#define BN 32                    // neighbor tile

// Scratch (device globals: no allocation allowed)
__device__ float g_xatt[NROWS * H];
__device__ float g_natt[NN * H];
__device__ float g_agg[NROWS * DIN];
__device__ float g_pacc[NSPLIT * NROWS * DIN];   // 16 MB partial accumulators
__device__ float g_pm[NSPLIT * NROWS];
__device__ float g_pl[NSPLIT * NROWS];
__device__ float g_fcp[2 * NROWS * DOUT];        // fc K-split partials (4 MB)

// ---- packed f32x2 helpers (sm_103a): 2 FMA per fma-pipe issue ------------
__device__ __forceinline__ void fma2(unsigned long long& d,
                                     unsigned long long a,
                                     unsigned long long b) {
    asm("fma.rn.f32x2 %0, %1, %2, %0;" : "+l"(d) : "l"(a), "l"(b));
}
__device__ __forceinline__ void mul2(unsigned long long& d,
                                     unsigned long long a) {
    asm("mul.rn.f32x2 %0, %0, %1;" : "+l"(d) : "l"(a));
}
__device__ __forceinline__ unsigned long long bcast2(float v) {
    unsigned long long r;
    asm("mov.b64 %0, {%1, %1};" : "=l"(r) : "r"(__float_as_uint(v)));
    return r;
}
__device__ __forceinline__ float2 unpack2(unsigned long long v) {
    float2 f;
    unsigned lo, hi;
    asm("mov.b64 {%0, %1}, %2;" : "=r"(lo), "=r"(hi) : "l"(v));
    f.x = __uint_as_float(lo); f.y = __uint_as_float(hi);
    return f;
}

// ---------------------------------------------------------------------------
// Kernel 1: both attention MLPs in one launch (grid = 512).
// ---------------------------------------------------------------------------
__global__ __launch_bounds__(256) void att_mlp_kernel(
        const float* __restrict__ x, const float* __restrict__ neibs,
        const float* __restrict__ xw1, const float* __restrict__ xb1,
        const float* __restrict__ xw2, const float* __restrict__ xb2,
        const float* __restrict__ nw1, const float* __restrict__ nb1,
        const float* __restrict__ nw2, const float* __restrict__ nb2) {
    __shared__ float w1s[DIN * H];
    __shared__ float w2s[H * H];
    __shared__ float b1s[H], b2s[H];
    __shared__ float xs[8 * DIN];
    __shared__ float t1s[8 * 33];

    const int tid = threadIdx.x;
    const int which = blockIdx.x >= 256;
    const int row0 = (blockIdx.x & 255) * 8;

    const float* in = which ? neibs : x;
    const float* w1 = which ? nw1 : xw1;
    const float* b1 = which ? nb1 : xb1;
    const float* w2 = which ? nw2 : xw2;
    const float* b2 = which ? nb2 : xb2;

    for (int i = tid; i < DIN * H; i += 256) w1s[i] = w1[i];
    for (int i = tid; i < H * H; i += 256)   w2s[i] = w2[i];
    if (tid < H) { b1s[tid] = b1[tid]; b2s[tid] = b2[tid]; }
    for (int i = tid; i < 8 * DIN; i += 256) xs[i] = in[row0 * DIN + i];
    __syncthreads();

    const int r = tid >> 5;
    const int h = tid & 31;

    float acc = b1s[h];
    #pragma unroll 8
    for (int k = 0; k < DIN; k++)
        acc += xs[r * DIN + k] * w1s[k * H + h];

    t1s[r * 33 + h] = tanhf(acc);
    __syncwarp();

    float acc2 = b2s[h];
    #pragma unroll
    for (int kk = 0; kk < H; kk++)
        acc2 += t1s[r * 33 + kk] * w2s[kk * H + h];

    float* out = which ? g_natt : g_xatt;
    out[(row0 + r) * H + h] = acc2;
}

// ---------------------------------------------------------------------------
// Kernel 2: split-K flash aggregation, f32x2 accumulate.
// Grid = 64 row-blocks * 8 splits = 512 blocks, 256 threads.
// ---------------------------------------------------------------------------
__global__ __launch_bounds__(256) void flash_part_kernel(
        const float* __restrict__ neibs, const float* __restrict__ mask) {
    __shared__ float naT[H * 36];       // transposed neib_att tile, padded
    __shared__ float ps[BM * 33];       // softmax weights
    __shared__ float nb[BN * DIN];      // 32 KB neighbor features
    __shared__ float m_s[BM], l_s[BM], alpha_s[BM];

    const int tid   = threadIdx.x;
    const int split = blockIdx.x & (NSPLIT - 1);
    const int row0  = (blockIdx.x >> 3) * BM;
    const int jstart = split * CHUNK;

    const int srow = tid >> 3;          // score row (0..31)
    const int jg   = tid & 7;
    const int j0   = jg * 4;

    const int rg = tid >> 5;            // acc: warp rg owns rows rg*4..+3
    const int cg = tid & 31;            // cols cg*4 and 128+cg*4

    float xr[H];
    {
        const float4* src = (const float4*)(g_xatt + (size_t)(row0 + srow) * H);
        #pragma unroll
        for (int i = 0; i < H / 4; i++) {
            float4 v = src[i];
            xr[i * 4 + 0] = v.x; xr[i * 4 + 1] = v.y;
            xr[i * 4 + 2] = v.z; xr[i * 4 + 3] = v.w;
        }
    }
    if (tid < BM) { m_s[tid] = -INFINITY; l_s[tid] = 0.0f; }

    unsigned long long accp[4][4];      // 4 rows x 4 f32x2 pairs (8 cols)
    #pragma unroll
    for (int i = 0; i < 4; i++)
        #pragma unroll
        for (int c = 0; c < 4; c++) accp[i][c] = 0ULL;

    __syncthreads();

    for (int t = 0; t < CHUNK / BN; t++) {
        const int jcol0 = jstart + t * BN;

        // prefetch this tile's mask into registers (overlaps staging)
        float4 mv = *(const float4*)(mask + (size_t)(row0 + srow) * NN + jcol0 + j0);

        // stage neib_att tile transposed: naT[h][j]
        for (int i = tid; i < BN * H; i += 256) {
            int j = i & 31, hh = i >> 5;
            naT[hh * 36 + j] = g_natt[(size_t)(jcol0 + j) * H + hh];
        }
        // stage neighbor features
        {
            const float4* src = (const float4*)(neibs + (size_t)jcol0 * DIN);
            float4* dst = (float4*)nb;
            #pragma unroll
            for (int i = tid; i < BN * DIN / 4; i += 256) dst[i] = src[i];
        }
        __syncthreads();

        // ---- scores: 4 j's per thread ----
        float s0 = 0.f, s1 = 0.f, s2 = 0.f, s3 = 0.f;
        #pragma unroll
        for (int hh = 0; hh < H; hh++) {
            float4 nv = *(const float4*)(naT + hh * 36 + j0);
            float xv = xr[hh];
            s0 += xv * nv.x; s1 += xv * nv.y;
            s2 += xv * nv.z; s3 += xv * nv.w;
        }
        s0 *= mv.x; s1 *= mv.y; s2 *= mv.z; s3 *= mv.w;

        float tm = fmaxf(fmaxf(s0, s1), fmaxf(s2, s3));
        #pragma unroll
        for (int d = 4; d >= 1; d >>= 1)
            tm = fmaxf(tm, __shfl_xor_sync(0xffffffffu, tm, d));

        float m_old = m_s[srow];
        float m_new = fmaxf(m_old, tm);
        float p0 = __expf(s0 - m_new);
        float p1 = __expf(s1 - m_new);
        float p2 = __expf(s2 - m_new);
        float p3 = __expf(s3 - m_new);
        ps[srow * 33 + j0 + 0] = p0;
        ps[srow * 33 + j0 + 1] = p1;
        ps[srow * 33 + j0 + 2] = p2;
        ps[srow * 33 + j0 + 3] = p3;

        float psum = (p0 + p1) + (p2 + p3);
        #pragma unroll
        for (int d = 4; d >= 1; d >>= 1)
            psum += __shfl_xor_sync(0xffffffffu, psum, d);

        if (jg == 0) {
            float alpha = __expf(m_old - m_new);
            l_s[srow] = l_s[srow] * alpha + psum;
            alpha_s[srow] = alpha;
            m_s[srow] = m_new;
        }
        __syncwarp();   // softmax state is warp-private

        // ---- rescale + accumulate p @ neibs_tile (f32x2) ----
        #pragma unroll
        for (int i = 0; i < 4; i++) {
            unsigned long long a2 = bcast2(alpha_s[rg * 4 + i]);
            #pragma unroll
            for (int c = 0; c < 4; c++) mul2(accp[i][c], a2);
        }

        #pragma unroll 4
        for (int j = 0; j < BN; j++) {
            ulonglong2 nA = *(const ulonglong2*)(nb + j * DIN + cg * 4);
            ulonglong2 nB = *(const ulonglong2*)(nb + j * DIN + 128 + cg * 4);
            #pragma unroll
            for (int i = 0; i < 4; i++) {
                unsigned long long p2v = bcast2(ps[(rg * 4 + i) * 33 + j]);
                fma2(accp[i][0], p2v, nA.x);
                fma2(accp[i][1], p2v, nA.y);
                fma2(accp[i][2], p2v, nB.x);
                fma2(accp[i][3], p2v, nB.y);
            }
        }
        __syncthreads();
    }

    // partial outputs
    #pragma unroll
    for (int i = 0; i < 4; i++) {
        const size_t base = ((size_t)split * NROWS + row0 + rg * 4 + i) * DIN;
        float2 v0 = unpack2(accp[i][0]);
        float2 v1 = unpack2(accp[i][1]);
        float2 v2 = unpack2(accp[i][2]);
        float2 v3 = unpack2(accp[i][3]);
        *(float4*)(g_pacc + base + cg * 4) = make_float4(v0.x, v0.y, v1.x, v1.y);
        *(float4*)(g_pacc + base + 128 + cg * 4) = make_float4(v2.x, v2.y, v3.x, v3.y);
    }
    if (jg == 0) {
        g_pm[split * NROWS + row0 + srow] = m_s[srow];
        g_pl[split * NROWS + row0 + srow] = l_s[srow];
    }
}

// ---------------------------------------------------------------------------
// Kernel 3: combine split partials -> agg = sigmoid(softmax @ neibs)
// ---------------------------------------------------------------------------
__global__ __launch_bounds__(256) void combine_kernel() {
    const int tid  = threadIdx.x;
    const int row  = blockIdx.x * 8 + (tid >> 5);
    const int lane = tid & 31;

    float M = -INFINITY;
    #pragma unroll
    for (int s = 0; s < NSPLIT; s++)
        M = fmaxf(M, g_pm[s * NROWS + row]);

    float w[NSPLIT];
    float L = 0.0f;
    #pragma unroll
    for (int s = 0; s < NSPLIT; s++) {
        w[s] = __expf(g_pm[s * NROWS + row] - M);
        L += g_pl[s * NROWS + row] * w[s];
    }
    const float invL = 1.0f / L;

    #pragma unroll
    for (int half = 0; half < 2; half++) {
        const int c = half * 128 + lane * 4;
        float4 a = make_float4(0.f, 0.f, 0.f, 0.f);
        #pragma unroll
        for (int s = 0; s < NSPLIT; s++) {
            float4 v = *(const float4*)(g_pacc + ((size_t)s * NROWS + row) * DIN + c);
            a.x += w[s] * v.x; a.y += w[s] * v.y;
            a.z += w[s] * v.z; a.w += w[s] * v.w;
        }
        float4 o;
        o.x = 1.0f / (1.0f + __expf(-a.x * invL));
        o.y = 1.0f / (1.0f + __expf(-a.y * invL));
        o.z = 1.0f / (1.0f + __expf(-a.z * invL));
        o.w = 1.0f / (1.0f + __expf(-a.w * invL));
        *(float4*)(g_agg + (size_t)row * DIN + c) = o;
    }
}

// ---------------------------------------------------------------------------
// Kernel 4a: fc partial GEMM, K split in 2 (x-half / agg-half).
// Grid = 64 rowblocks * 4 colblocks * 2 ksplit = 512 blocks, 128 threads.
// Thread computes 4 rows x 4 cols via f32x2.
// ---------------------------------------------------------------------------
__global__ __launch_bounds__(128) void fc_part_kernel(
        const float* __restrict__ x, const float* __restrict__ fcw) {
    __shared__ float AtT[32 * 36];     // [k][row], padded, float4-aligned
    __shared__ float Wt[32 * 64];

    const int b    = blockIdx.x;
    const int ks   = b & 1;
    const int col0 = ((b >> 1) & 3) * 64;
    const int row0 = (b >> 3) * 32;

    const float* A = ks ? g_agg : x;                       // [2048, 256]
    const float* W = fcw + (size_t)ks * DIN * DOUT;        // rows [ks*256, +256)

    const int tid = threadIdx.x;
    const int rg  = tid >> 4;          // 0..7 -> rows rg*4..+3
    const int cq  = tid & 15;          // 0..15 -> cols cq*4..+3

    unsigned long long acc[4][2];
    #pragma unroll
    for (int i = 0; i < 4; i++) { acc[i][0] = 0ULL; acc[i][1] = 0ULL; }

    for (int kt = 0; kt < 8; kt++) {
        const int kbase = kt * 32;
        // stage A transposed
        for (int i = tid; i < 32 * 32; i += 128) {
            int r = i >> 5, kk = i & 31;
            AtT[kk * 36 + r] = A[(size_t)(row0 + r) * DIN + kbase + kk];
        }
        // stage W tile
        #pragma unroll
        for (int i = tid; i < 32 * 64 / 4; i += 128) {
            int kk = i >> 4, cc = (i & 15) * 4;
            *(float4*)(Wt + kk * 64 + cc) =
                *(const float4*)(W + (size_t)(kbase + kk) * DOUT + col0 + cc);
        }
        __syncthreads();

        #pragma unroll 8
        for (int k = 0; k < 32; k++) {
            float4 av = *(const float4*)(AtT + k * 36 + rg * 4);
            ulonglong2 wv = *(const ulonglong2*)(Wt + k * 64 + cq * 4);
            unsigned long long a0 = bcast2(av.x);
            unsigned long long a1 = bcast2(av.y);
            unsigned long long a2 = bcast2(av.z);
            unsigned long long a3 = bcast2(av.w);
            fma2(acc[0][0], a0, wv.x); fma2(acc[0][1], a0, wv.y);
            fma2(acc[1][0], a1, wv.x); fma2(acc[1][1], a1, wv.y);
            fma2(acc[2][0], a2, wv.x); fma2(acc[2][1], a2, wv.y);
            fma2(acc[3][0], a3, wv.x); fma2(acc[3][1], a3, wv.y);
        }
        __syncthreads();
    }

    #pragma unroll
    for (int i = 0; i < 4; i++) {
        float2 lo = unpack2(acc[i][0]);
        float2 hi = unpack2(acc[i][1]);
        *(float4*)(g_fcp + ((size_t)ks * NROWS + row0 + rg * 4 + i) * DOUT
                   + col0 + cq * 4) = make_float4(lo.x, lo.y, hi.x, hi.y);
    }
}

// ---------------------------------------------------------------------------
// Kernel 4b: out = sigmoid(part0 + part1 + b)
// ---------------------------------------------------------------------------
__global__ __launch_bounds__(256) void fc_epilogue_kernel(
        const float* __restrict__ fcb, float* __restrict__ out) {
    const int idx4 = blockIdx.x * 256 + threadIdx.x;   // 512 blocks
    const int off  = idx4 * 4;
    const int col  = off & (DOUT - 1);

    float4 p0 = *(const float4*)(g_fcp + off);
    float4 p1 = *(const float4*)(g_fcp + NROWS * DOUT + off);
    float4 b4 = *(const float4*)(fcb + col);
    float4 o;
    o.x = 1.0f / (1.0f + __expf(-(p0.x + p1.x + b4.x)));
    o.y = 1.0f / (1.0f + __expf(-(p0.y + p1.y + b4.y)));
    o.z = 1.0f / (1.0f + __expf(-(p0.z + p1.z + b4.z)));
    o.w = 1.0f / (1.0f + __expf(-(p0.w + p1.w + b4.w)));
    *(float4*)(out + off) = o;
}

// ---------------------------------------------------------------------------
extern "C" void kernel_launch(void* const* d_in, const int* in_sizes, int n_in,
                              void* d_out, int out_size) {
    (void)in_sizes; (void)n_in; (void)out_size;
    const float* x      = (const float*)d_in[0];
    const float* neibs  = (const float*)d_in[1];
    // d_in[2] = edge_emb: dead code in the reference, intentionally untouched
    const float* mask   = (const float*)d_in[3];
    const float* ax_w1  = (const float*)d_in[4];
    const float* ax_b1  = (const float*)d_in[5];
    const float* ax_w2  = (const float*)d_in[6];
    const float* ax_b2  = (const float*)d_in[7];
    const float* an_w1  = (const float*)d_in[8];
    const float* an_b1  = (const float*)d_in[9];
    const float* an_w2  = (const float*)d_in[10];
    const float* an_b2  = (const float*)d_in[11];
    // d_in[12..15] = ae_* : dead code
    const float* fcx_w  = (const float*)d_in[16];
    const float* fcx_b  = (const float*)d_in[17];
    float* out = (float*)d_out;

    att_mlp_kernel<<<512, 256>>>(x, neibs, ax_w1, ax_b1, ax_w2, ax_b2,
                                 an_w1, an_b1, an_w2, an_b2);
    flash_part_kernel<<<(NROWS / BM) * NSPLIT, 256>>>(neibs, mask);
    combine_kernel<<<NROWS / 8, 256>>>();
    fc_part_kernel<<<(NROWS / 32) * (DOUT / 64) * 2, 128>>>(x, fcx_w);
    fc_epilogue_kernel<<<NROWS * DOUT / 1024, 256>>>(fcx_b, out);
}

// round 9
// speedup vs baseline: 3.4590x; 1.3186x over previous
#include <cuda_runtime.h>
#include <math.h>

// Problem constants
#define NROWS 2048
#define NN    2048
#define DIN   256
#define H     32
#define DOUT  256

#define NSPLIT 8
#define CHUNK  (NN / NSPLIT)     // 256 neighbors per split
#define BM 32                    // rows per flash block
#define BN 32                    // neighbor tile
#define NBS (DIN + 8)            // nb smem stride (conflict-free B frags)

// Scratch (device globals: no allocation allowed)
__device__ float g_xatt[NROWS * H];
__device__ float g_natt[NN * H];
__device__ float g_agg[NROWS * DIN];
__device__ float g_pacc[NSPLIT * NROWS * DIN];   // 16 MB partial accumulators
__device__ float g_pm[NSPLIT * NROWS];
__device__ float g_pl[NSPLIT * NROWS];
__device__ float g_fcp[2 * NROWS * DOUT];        // fc K-split partials (4 MB)

// ---- tf32 mma helpers -----------------------------------------------------
__device__ __forceinline__ unsigned f2t(float f) {
    unsigned r;
    asm("cvt.rn.tf32.f32 %0, %1;" : "=r"(r) : "f"(f));
    return r;
}
__device__ __forceinline__ void mma8(float4& d,
                                     unsigned a0, unsigned a1,
                                     unsigned a2, unsigned a3,
                                     unsigned b0, unsigned b1) {
    asm("mma.sync.aligned.m16n8k8.row.col.f32.tf32.tf32.f32 "
        "{%0,%1,%2,%3}, {%4,%5,%6,%7}, {%8,%9}, {%0,%1,%2,%3};"
        : "+f"(d.x), "+f"(d.y), "+f"(d.z), "+f"(d.w)
        : "r"(a0), "r"(a1), "r"(a2), "r"(a3), "r"(b0), "r"(b1));
}
__device__ __forceinline__ unsigned fu(float f) { return __float_as_uint(f); }

// ---------------------------------------------------------------------------
// Kernel 1: both attention MLPs in one launch (grid = 512).
// ---------------------------------------------------------------------------
__global__ __launch_bounds__(256) void att_mlp_kernel(
        const float* __restrict__ x, const float* __restrict__ neibs,
        const float* __restrict__ xw1, const float* __restrict__ xb1,
        const float* __restrict__ xw2, const float* __restrict__ xb2,
        const float* __restrict__ nw1, const float* __restrict__ nb1,
        const float* __restrict__ nw2, const float* __restrict__ nb2) {
    __shared__ float w1s[DIN * H];
    __shared__ float w2s[H * H];
    __shared__ float b1s[H], b2s[H];
    __shared__ float xs[8 * DIN];
    __shared__ float t1s[8 * 33];

    const int tid = threadIdx.x;
    const int which = blockIdx.x >= 256;
    const int row0 = (blockIdx.x & 255) * 8;

    const float* in = which ? neibs : x;
    const float* w1 = which ? nw1 : xw1;
    const float* b1 = which ? nb1 : xb1;
    const float* w2 = which ? nw2 : xw2;
    const float* b2 = which ? nb2 : xb2;

    for (int i = tid; i < DIN * H; i += 256) w1s[i] = w1[i];
    for (int i = tid; i < H * H; i += 256)   w2s[i] = w2[i];
    if (tid < H) { b1s[tid] = b1[tid]; b2s[tid] = b2[tid]; }
    for (int i = tid; i < 8 * DIN; i += 256) xs[i] = in[row0 * DIN + i];
    __syncthreads();

    const int r = tid >> 5;
    const int h = tid & 31;

    float acc = b1s[h];
    #pragma unroll 8
    for (int k = 0; k < DIN; k++)
        acc += xs[r * DIN + k] * w1s[k * H + h];

    t1s[r * 33 + h] = tanhf(acc);
    __syncwarp();

    float acc2 = b2s[h];
    #pragma unroll
    for (int kk = 0; kk < H; kk++)
        acc2 += t1s[r * 33 + kk] * w2s[kk * H + h];

    float* out = which ? g_natt : g_xatt;
    out[(row0 + r) * H + h] = acc2;
}

// ---------------------------------------------------------------------------
// Kernel 2: split-K flash aggregation. Scores SIMT fp32; PV via tf32 MMA.
// Grid = 64 row-blocks * 8 splits = 512 blocks, 256 threads (8 warps).
// Warp w owns output n-slice [w*32, w*32+32).
// ---------------------------------------------------------------------------
__global__ __launch_bounds__(256) void flash_part_kernel(
        const float* __restrict__ neibs, const float* __restrict__ mask) {
    __shared__ float naT[H * 36];       // transposed neib_att tile (fp32)
    __shared__ float ps[BM * 36];       // softmax weights (tf32 bits)
    __shared__ float nb[BN * NBS];      // neighbor features (tf32 bits) 33 KB
    __shared__ float m_s[BM], l_s[BM], alpha_s[BM];

    const int tid   = threadIdx.x;
    const int split = blockIdx.x & (NSPLIT - 1);
    const int row0  = (blockIdx.x >> 3) * BM;
    const int jstart = split * CHUNK;

    // score-phase mapping: 32 rows x 8 j-groups of 4
    const int srow = tid >> 3;
    const int jg   = tid & 7;
    const int j0   = jg * 4;

    // mma mapping
    const int warp = tid >> 5;
    const int lane = tid & 31;
    const int gid  = lane >> 2;         // group id (0..7)
    const int tg   = lane & 3;          // thread in group
    const int n0   = warp * 32;

    float xr[H];
    {
        const float4* src = (const float4*)(g_xatt + (size_t)(row0 + srow) * H);
        #pragma unroll
        for (int i = 0; i < H / 4; i++) {
            float4 v = src[i];
            xr[i * 4 + 0] = v.x; xr[i * 4 + 1] = v.y;
            xr[i * 4 + 2] = v.z; xr[i * 4 + 3] = v.w;
        }
    }
    if (tid < BM) { m_s[tid] = -INFINITY; l_s[tid] = 0.0f; }

    float4 acc[2][4];                   // [m-tile][n-tile]
    #pragma unroll
    for (int mt = 0; mt < 2; mt++)
        #pragma unroll
        for (int nt = 0; nt < 4; nt++)
            acc[mt][nt] = make_float4(0.f, 0.f, 0.f, 0.f);

    __syncthreads();

    for (int t = 0; t < CHUNK / BN; t++) {
        const int jcol0 = jstart + t * BN;

        // prefetch this tile's mask into registers (overlaps staging)
        float4 mv = *(const float4*)(mask + (size_t)(row0 + srow) * NN + jcol0 + j0);

        // stage neib_att tile transposed (fp32, score phase)
        for (int i = tid; i < BN * H; i += 256) {
            int j = i & 31, hh = i >> 5;
            naT[hh * 36 + j] = g_natt[(size_t)(jcol0 + j) * H + hh];
        }
        // stage neighbor features, converted to tf32, stride NBS
        #pragma unroll
        for (int i = tid; i < BN * DIN / 4; i += 256) {
            int j = i >> 6, c4 = (i & 63) * 4;
            float4 v = *(const float4*)(neibs + (size_t)(jcol0 + j) * DIN + c4);
            float* dst = nb + j * NBS + c4;
            dst[0] = __uint_as_float(f2t(v.x));
            dst[1] = __uint_as_float(f2t(v.y));
            dst[2] = __uint_as_float(f2t(v.z));
            dst[3] = __uint_as_float(f2t(v.w));
        }
        __syncthreads();

        // ---- scores (SIMT fp32): 4 j's per thread ----
        float s0 = 0.f, s1 = 0.f, s2 = 0.f, s3 = 0.f;
        #pragma unroll
        for (int hh = 0; hh < H; hh++) {
            float4 nv = *(const float4*)(naT + hh * 36 + j0);
            float xv = xr[hh];
            s0 += xv * nv.x; s1 += xv * nv.y;
            s2 += xv * nv.z; s3 += xv * nv.w;
        }
        s0 *= mv.x; s1 *= mv.y; s2 *= mv.z; s3 *= mv.w;

        float tm = fmaxf(fmaxf(s0, s1), fmaxf(s2, s3));
        #pragma unroll
        for (int d = 4; d >= 1; d >>= 1)
            tm = fmaxf(tm, __shfl_xor_sync(0xffffffffu, tm, d));

        float m_old = m_s[srow];
        float m_new = fmaxf(m_old, tm);
        float p0 = __expf(s0 - m_new);
        float p1 = __expf(s1 - m_new);
        float p2 = __expf(s2 - m_new);
        float p3 = __expf(s3 - m_new);
        ps[srow * 36 + j0 + 0] = __uint_as_float(f2t(p0));
        ps[srow * 36 + j0 + 1] = __uint_as_float(f2t(p1));
        ps[srow * 36 + j0 + 2] = __uint_as_float(f2t(p2));
        ps[srow * 36 + j0 + 3] = __uint_as_float(f2t(p3));

        float psum = (p0 + p1) + (p2 + p3);
        #pragma unroll
        for (int d = 4; d >= 1; d >>= 1)
            psum += __shfl_xor_sync(0xffffffffu, psum, d);

        if (jg == 0) {
            float alpha = __expf(m_old - m_new);   // 0 on first tile
            l_s[srow] = l_s[srow] * alpha + psum;
            alpha_s[srow] = alpha;
            m_s[srow] = m_new;
        }
        __syncthreads();   // ps/alpha visible to all warps (A frags span 32 rows)

        // ---- rescale accumulators by per-row alpha ----
        {
            float aA = alpha_s[gid];
            float aB = alpha_s[gid + 8];
            float aC = alpha_s[gid + 16];
            float aD = alpha_s[gid + 24];
            #pragma unroll
            for (int nt = 0; nt < 4; nt++) {
                acc[0][nt].x *= aA; acc[0][nt].y *= aA;
                acc[0][nt].z *= aB; acc[0][nt].w *= aB;
                acc[1][nt].x *= aC; acc[1][nt].y *= aC;
                acc[1][nt].z *= aD; acc[1][nt].w *= aD;
            }
        }

        // ---- PV: tf32 mma, K = 32 in 4 steps of 8 ----
        #pragma unroll
        for (int kt = 0; kt < 4; kt++) {
            const int kc = kt * 8 + tg;
            unsigned a0m0 = fu(ps[gid * 36 + kc]);
            unsigned a1m0 = fu(ps[(gid + 8) * 36 + kc]);
            unsigned a2m0 = fu(ps[gid * 36 + kc + 4]);
            unsigned a3m0 = fu(ps[(gid + 8) * 36 + kc + 4]);
            unsigned a0m1 = fu(ps[(gid + 16) * 36 + kc]);
            unsigned a1m1 = fu(ps[(gid + 24) * 36 + kc]);
            unsigned a2m1 = fu(ps[(gid + 16) * 36 + kc + 4]);
            unsigned a3m1 = fu(ps[(gid + 24) * 36 + kc + 4]);
            #pragma unroll
            for (int nt = 0; nt < 4; nt++) {
                const int nc = n0 + nt * 8 + gid;
                unsigned b0 = fu(nb[(kt * 8 + tg) * NBS + nc]);
                unsigned b1 = fu(nb[(kt * 8 + tg + 4) * NBS + nc]);
                mma8(acc[0][nt], a0m0, a1m0, a2m0, a3m0, b0, b1);
                mma8(acc[1][nt], a0m1, a1m1, a2m1, a3m1, b0, b1);
            }
        }
        __syncthreads();
    }

    // partial outputs (fragment layout -> g_pacc)
    #pragma unroll
    for (int mt = 0; mt < 2; mt++) {
        const int r1 = gid + mt * 16;
        const int r2 = gid + 8 + mt * 16;
        const size_t b1 = ((size_t)split * NROWS + row0 + r1) * DIN;
        const size_t b2 = ((size_t)split * NROWS + row0 + r2) * DIN;
        #pragma unroll
        for (int nt = 0; nt < 4; nt++) {
            const int c = n0 + nt * 8 + 2 * tg;
            *(float2*)(g_pacc + b1 + c) = make_float2(acc[mt][nt].x, acc[mt][nt].y);
            *(float2*)(g_pacc + b2 + c) = make_float2(acc[mt][nt].z, acc[mt][nt].w);
        }
    }
    if (tid < BM) {
        g_pm[split * NROWS + row0 + tid] = m_s[tid];
        g_pl[split * NROWS + row0 + tid] = l_s[tid];
    }
}

// ---------------------------------------------------------------------------
// Kernel 3: combine split partials -> agg = sigmoid(softmax @ neibs)
// ---------------------------------------------------------------------------
__global__ __launch_bounds__(256) void combine_kernel() {
    const int tid  = threadIdx.x;
    const int row  = blockIdx.x * 8 + (tid >> 5);
    const int lane = tid & 31;

    float M = -INFINITY;
    #pragma unroll
    for (int s = 0; s < NSPLIT; s++)
        M = fmaxf(M, g_pm[s * NROWS + row]);

    float w[NSPLIT];
    float L = 0.0f;
    #pragma unroll
    for (int s = 0; s < NSPLIT; s++) {
        w[s] = __expf(g_pm[s * NROWS + row] - M);
        L += g_pl[s * NROWS + row] * w[s];
    }
    const float invL = 1.0f / L;

    #pragma unroll
    for (int half = 0; half < 2; half++) {
        const int c = half * 128 + lane * 4;
        float4 a = make_float4(0.f, 0.f, 0.f, 0.f);
        #pragma unroll
        for (int s = 0; s < NSPLIT; s++) {
            float4 v = *(const float4*)(g_pacc + ((size_t)s * NROWS + row) * DIN + c);
            a.x += w[s] * v.x; a.y += w[s] * v.y;
            a.z += w[s] * v.z; a.w += w[s] * v.w;
        }
        float4 o;
        o.x = 1.0f / (1.0f + __expf(-a.x * invL));
        o.y = 1.0f / (1.0f + __expf(-a.y * invL));
        o.z = 1.0f / (1.0f + __expf(-a.z * invL));
        o.w = 1.0f / (1.0f + __expf(-a.w * invL));
        *(float4*)(g_agg + (size_t)row * DIN + c) = o;
    }
}

// ---------------------------------------------------------------------------
// Kernel 4a: fc partial GEMM via tf32 mma. K split in 2 (x-half / agg-half).
// Tile 32 rows x 64 cols; 128 threads (4 warps, warp = n-slice of 16).
// Grid = 64 * 4 * 2 = 512 blocks.
// ---------------------------------------------------------------------------
__global__ __launch_bounds__(128) void fc_part_kernel(
        const float* __restrict__ x, const float* __restrict__ fcw) {
    __shared__ float As[32 * 36];      // tf32 bits, conflict-free A frags
    __shared__ float Ws[32 * 72];      // tf32 bits, conflict-free B frags

    const int b    = blockIdx.x;
    const int ks   = b & 1;
    const int col0 = ((b >> 1) & 3) * 64;
    const int row0 = (b >> 3) * 32;

    const float* A = ks ? g_agg : x;
    const float* W = fcw + (size_t)ks * DIN * DOUT;

    const int tid  = threadIdx.x;
    const int warp = tid >> 5;
    const int lane = tid & 31;
    const int gid  = lane >> 2;
    const int tg   = lane & 3;
    const int n0   = warp * 16;

    float4 acc[2][2];
    #pragma unroll
    for (int mt = 0; mt < 2; mt++)
        #pragma unroll
        for (int nt = 0; nt < 2; nt++)
            acc[mt][nt] = make_float4(0.f, 0.f, 0.f, 0.f);

    for (int kt8 = 0; kt8 < 8; kt8++) {
        const int kbase = kt8 * 32;
        // stage A (32 rows x 32 k), cvt tf32
        for (int i = tid; i < 32 * 32; i += 128) {
            int r = i >> 5, kk = i & 31;
            As[r * 36 + kk] =
                __uint_as_float(f2t(A[(size_t)(row0 + r) * DIN + kbase + kk]));
        }
        // stage W (32 k x 64 n), cvt tf32
        #pragma unroll
        for (int i = tid; i < 32 * 64 / 4; i += 128) {
            int kk = i >> 4, cc = (i & 15) * 4;
            float4 v = *(const float4*)(W + (size_t)(kbase + kk) * DOUT + col0 + cc);
            float* dst = Ws + kk * 72 + cc;
            dst[0] = __uint_as_float(f2t(v.x));
            dst[1] = __uint_as_float(f2t(v.y));
            dst[2] = __uint_as_float(f2t(v.z));
            dst[3] = __uint_as_float(f2t(v.w));
        }
        __syncthreads();

        #pragma unroll
        for (int kt = 0; kt < 4; kt++) {
            const int kc = kt * 8 + tg;
            unsigned a0m0 = fu(As[gid * 36 + kc]);
            unsigned a1m0 = fu(As[(gid + 8) * 36 + kc]);
            unsigned a2m0 = fu(As[gid * 36 + kc + 4]);
            unsigned a3m0 = fu(As[(gid + 8) * 36 + kc + 4]);
            unsigned a0m1 = fu(As[(gid + 16) * 36 + kc]);
            unsigned a1m1 = fu(As[(gid + 24) * 36 + kc]);
            unsigned a2m1 = fu(As[(gid + 16) * 36 + kc + 4]);
            unsigned a3m1 = fu(As[(gid + 24) * 36 + kc + 4]);
            #pragma unroll
            for (int nt = 0; nt < 2; nt++) {
                const int nc = n0 + nt * 8 + gid;
                unsigned b0 = fu(Ws[(kt * 8 + tg) * 72 + nc]);
                unsigned b1 = fu(Ws[(kt * 8 + tg + 4) * 72 + nc]);
                mma8(acc[0][nt], a0m0, a1m0, a2m0, a3m0, b0, b1);
                mma8(acc[1][nt], a0m1, a1m1, a2m1, a3m1, b0, b1);
            }
        }
        __syncthreads();
    }

    #pragma unroll
    for (int mt = 0; mt < 2; mt++) {
        const int r1 = gid + mt * 16;
        const int r2 = gid + 8 + mt * 16;
        const size_t o1 = ((size_t)ks * NROWS + row0 + r1) * DOUT + col0;
        const size_t o2 = ((size_t)ks * NROWS + row0 + r2) * DOUT + col0;
        #pragma unroll
        for (int nt = 0; nt < 2; nt++) {
            const int c = n0 + nt * 8 + 2 * tg;
            *(float2*)(g_fcp + o1 + c) = make_float2(acc[mt][nt].x, acc[mt][nt].y);
            *(float2*)(g_fcp + o2 + c) = make_float2(acc[mt][nt].z, acc[mt][nt].w);
        }
    }
}

// ---------------------------------------------------------------------------
// Kernel 4b: out = sigmoid(part0 + part1 + b)
// ---------------------------------------------------------------------------
__global__ __launch_bounds__(256) void fc_epilogue_kernel(
        const float* __restrict__ fcb, float* __restrict__ out) {
    const int idx4 = blockIdx.x * 256 + threadIdx.x;
    const int off  = idx4 * 4;
    const int col  = off & (DOUT - 1);

    float4 p0 = *(const float4*)(g_fcp + off);
    float4 p1 = *(const float4*)(g_fcp + NROWS * DOUT + off);
    float4 b4 = *(const float4*)(fcb + col);
    float4 o;
    o.x = 1.0f / (1.0f + __expf(-(p0.x + p1.x + b4.x)));
    o.y = 1.0f / (1.0f + __expf(-(p0.y + p1.y + b4.y)));
    o.z = 1.0f / (1.0f + __expf(-(p0.z + p1.z + b4.z)));
    o.w = 1.0f / (1.0f + __expf(-(p0.w + p1.w + b4.w)));
    *(float4*)(out + off) = o;
}

// ---------------------------------------------------------------------------
extern "C" void kernel_launch(void* const* d_in, const int* in_sizes, int n_in,
                              void* d_out, int out_size) {
    (void)in_sizes; (void)n_in; (void)out_size;
    const float* x      = (const float*)d_in[0];
    const float* neibs  = (const float*)d_in[1];
    // d_in[2] = edge_emb: dead code in the reference, intentionally untouched
    const float* mask   = (const float*)d_in[3];
    const float* ax_w1  = (const float*)d_in[4];
    const float* ax_b1  = (const float*)d_in[5];
    const float* ax_w2  = (const float*)d_in[6];
    const float* ax_b2  = (const float*)d_in[7];
    const float* an_w1  = (const float*)d_in[8];
    const float* an_b1  = (const float*)d_in[9];
    const float* an_w2  = (const float*)d_in[10];
    const float* an_b2  = (const float*)d_in[11];
    // d_in[12..15] = ae_* : dead code
    const float* fcx_w  = (const float*)d_in[16];
    const float* fcx_b  = (const float*)d_in[17];
    float* out = (float*)d_out;

    att_mlp_kernel<<<512, 256>>>(x, neibs, ax_w1, ax_b1, ax_w2, ax_b2,
                                 an_w1, an_b1, an_w2, an_b2);
    flash_part_kernel<<<(NROWS / BM) * NSPLIT, 256>>>(neibs, mask);
    combine_kernel<<<NROWS / 8, 256>>>();
    fc_part_kernel<<<(NROWS / 32) * (DOUT / 64) * 2, 128>>>(x, fcx_w);
    fc_epilogue_kernel<<<NROWS * DOUT / 1024, 256>>>(fcx_b, out);
}